// round 15
// baseline (speedup 1.0000x reference)
#include <cuda_runtime.h>

#define NN 100000
#define NE 3200000
#define FH  128
#define FC  40

typedef long long ll;

// ---------------- scratch (device globals, no allocation) ----------------
__device__ int   g_is64;             // 1 if edge_index is int64, 0 if int32
__device__ int   g_deg[NN];          // in-degree (real edges)
__device__ int   g_off[NN + 1];      // CSR row offsets
__device__ int   g_cur[NN];          // scatter cursors
__device__ int   g_es[NE];           // CSR: src node per slot
__device__ float g_wt[NE];           // CSR: edge weight per slot
__device__ float g_dinv[NN];         // rsqrt(deg+1)
__device__ float g_h [NN * FH];      // x @ W1
__device__ float g_h1[NN * FH];      // relu(agg1 + b1)
__device__ float g_g [NN * FC];      // h1 @ W2

// ---------------- dtype detection ----------------
// If the buffer is really int64 (node ids < 2^31), every odd int32 word of the
// first 64 entries is 0. If it is int32, those words are random node ids.
__global__ void k_detect(const int* ei32) {
    if (threadIdx.x == 0 && blockIdx.x == 0) {
        int all0 = 1;
        for (int i = 1; i < 129; i += 2) all0 &= (ei32[i] == 0);
        g_is64 = all0;
    }
}

__device__ __forceinline__ int edge_at(const void* ei, int idx) {
    if (g_is64) return (int)((const ll*)ei)[idx];
    return ((const int*)ei)[idx];
}

// ---------------- degree histogram ----------------
__global__ void k_zero_deg() {
    int i = blockIdx.x * 256 + threadIdx.x;
    if (i < NN) g_deg[i] = 0;
}

__global__ void k_hist(const void* ei) {
    int i = blockIdx.x * 256 + threadIdx.x;
    if (i < NE) {
        int d = edge_at(ei, NE + i);     // dst row
        atomicAdd(&g_deg[d], 1);
    }
}

// ---------------- single-block exclusive scan (256 threads) ----------------
__global__ void k_scan() {
    __shared__ int part[256];
    const int T = 256;
    const int CH = (NN + T - 1) / T;   // 391
    int t = threadIdx.x;
    int beg = t * CH;
    int end = min(beg + CH, NN);

    int s = 0;
    for (int i = beg; i < end; i++) s += g_deg[i];
    part[t] = s;
    __syncthreads();
    for (int d = 1; d < T; d <<= 1) {
        int v = (t >= d) ? part[t - d] : 0;
        __syncthreads();
        part[t] += v;
        __syncthreads();
    }
    int base = part[t] - s;   // exclusive prefix of this chunk
    for (int i = beg; i < end; i++) {
        g_off[i] = base;
        g_cur[i] = base;
        base += g_deg[i];
    }
    if (t == T - 1) g_off[NN] = base;
}

// ---------------- dinv ----------------
__global__ void k_dinv() {
    int i = blockIdx.x * 256 + threadIdx.x;
    if (i < NN) g_dinv[i] = rsqrtf((float)(g_deg[i] + 1));
}

// ---------------- scatter edges into CSR buckets ----------------
__global__ void k_scatter(const void* ei) {
    int e = blockIdx.x * 256 + threadIdx.x;
    if (e < NE) {
        int s = edge_at(ei, e);          // src row
        int d = edge_at(ei, NE + e);     // dst row
        float w = g_dinv[s] * g_dinv[d];
        int pos = atomicAdd(&g_cur[d], 1);
        g_es[pos] = s;
        g_wt[pos] = w;
    }
}

// ---------------- GEMM1: g_h = x @ W1  (M=100000, K=128, N=128) ----------------
__global__ void k_gemm1(const float* __restrict__ x, const float* __restrict__ W) {
    __shared__ float xs[64][33];     // 64 rows x 32 k
    __shared__ float ws[32][132];    // 32 k x 128 cols (padded)

    int tid  = threadIdx.x;
    int row0 = blockIdx.x * 64;
    int ty = tid >> 4;   // 0..15
    int tx = tid & 15;   // 0..15

    float acc[4][8];
#pragma unroll
    for (int i = 0; i < 4; i++)
#pragma unroll
        for (int j = 0; j < 8; j++) acc[i][j] = 0.f;

    for (int kk = 0; kk < 128; kk += 32) {
        for (int i = tid; i < 64 * 32; i += 256) {
            int r = i >> 5, c = i & 31;
            int gr = row0 + r;
            xs[r][c] = (gr < NN) ? x[gr * 128 + kk + c] : 0.f;
        }
        for (int i = tid; i < 32 * 128; i += 256) {
            int r = i >> 7, c = i & 127;
            ws[r][c] = W[(kk + r) * 128 + c];
        }
        __syncthreads();

#pragma unroll
        for (int k = 0; k < 32; k++) {
            float a[4];
#pragma unroll
            for (int i = 0; i < 4; i++) a[i] = xs[ty * 4 + i][k];
            float b[8];
#pragma unroll
            for (int j = 0; j < 8; j++) b[j] = ws[k][tx + 16 * j];
#pragma unroll
            for (int i = 0; i < 4; i++)
#pragma unroll
                for (int j = 0; j < 8; j++) acc[i][j] = fmaf(a[i], b[j], acc[i][j]);
        }
        __syncthreads();
    }

#pragma unroll
    for (int i = 0; i < 4; i++) {
        int r = row0 + ty * 4 + i;
        if (r < NN) {
#pragma unroll
            for (int j = 0; j < 8; j++) g_h[r * 128 + tx + 16 * j] = acc[i][j];
        }
    }
}

// ---------------- agg layer 1: h1 = relu(sum_w h[src] + dinv^2 h[node] + b1) ----
__global__ void k_agg1(const float* __restrict__ b1) {
    int node = blockIdx.x;
    int c    = threadIdx.x;             // 0..127
    int beg  = g_off[node];
    int end  = g_off[node + 1];

    float a0 = 0.f, a1 = 0.f, a2 = 0.f, a3 = 0.f;
    int j = beg;
    for (; j + 3 < end; j += 4) {
        int   s0 = g_es[j],     s1 = g_es[j + 1], s2 = g_es[j + 2], s3 = g_es[j + 3];
        float w0 = g_wt[j],     w1 = g_wt[j + 1], w2 = g_wt[j + 2], w3 = g_wt[j + 3];
        a0 = fmaf(w0, g_h[s0 * FH + c], a0);
        a1 = fmaf(w1, g_h[s1 * FH + c], a1);
        a2 = fmaf(w2, g_h[s2 * FH + c], a2);
        a3 = fmaf(w3, g_h[s3 * FH + c], a3);
    }
    for (; j < end; j++)
        a0 = fmaf(g_wt[j], g_h[g_es[j] * FH + c], a0);

    float di = g_dinv[node];
    float acc = (a0 + a1) + (a2 + a3) + di * di * g_h[node * FH + c] + b1[c];
    g_h1[node * FH + c] = fmaxf(acc, 0.f);
}

// ---------------- GEMM2: g_g = h1 @ W2  (M=100000, K=128, N=40) ----------------
__global__ void k_gemm2(const float* __restrict__ W2) {
    __shared__ float hs[128][33];    // 128 rows x 32 k
    __shared__ float ws[32][40];     // 32 k x 40 cols

    int tid  = threadIdx.x;
    int row0 = blockIdx.x * 128;
    int ty = tid >> 3;   // 0..31
    int tx = tid & 7;    // 0..7

    float acc[4][5];
#pragma unroll
    for (int i = 0; i < 4; i++)
#pragma unroll
        for (int j = 0; j < 5; j++) acc[i][j] = 0.f;

    for (int kk = 0; kk < 128; kk += 32) {
        for (int i = tid; i < 128 * 32; i += 256) {
            int r = i >> 5, c = i & 31;
            int gr = row0 + r;
            hs[r][c] = (gr < NN) ? g_h1[gr * 128 + kk + c] : 0.f;
        }
        for (int i = tid; i < 32 * 40; i += 256) {
            int r = i / 40, c = i - r * 40;
            ws[r][c] = W2[(kk + r) * 40 + c];
        }
        __syncthreads();

#pragma unroll
        for (int k = 0; k < 32; k++) {
            float a[4];
#pragma unroll
            for (int i = 0; i < 4; i++) a[i] = hs[ty * 4 + i][k];
            float b[5];
#pragma unroll
            for (int j = 0; j < 5; j++) b[j] = ws[k][tx + 8 * j];
#pragma unroll
            for (int i = 0; i < 4; i++)
#pragma unroll
                for (int j = 0; j < 5; j++) acc[i][j] = fmaf(a[i], b[j], acc[i][j]);
        }
        __syncthreads();
    }

#pragma unroll
    for (int i = 0; i < 4; i++) {
        int r = row0 + ty * 4 + i;
        if (r < NN) {
#pragma unroll
            for (int j = 0; j < 5; j++) g_g[r * 40 + tx + 8 * j] = acc[i][j];
        }
    }
}

// ---------------- agg layer 2: out = sum_w g[src] + dinv^2 g[node] + b2 --------
__global__ void k_agg2(const float* __restrict__ b2, float* __restrict__ out) {
    int node = blockIdx.x;
    int c    = threadIdx.x;             // 64 threads, 0..39 active
    if (c >= FC) return;
    int beg  = g_off[node];
    int end  = g_off[node + 1];

    float a0 = 0.f, a1 = 0.f, a2 = 0.f, a3 = 0.f;
    int j = beg;
    for (; j + 3 < end; j += 4) {
        int   s0 = g_es[j],     s1 = g_es[j + 1], s2 = g_es[j + 2], s3 = g_es[j + 3];
        float w0 = g_wt[j],     w1 = g_wt[j + 1], w2 = g_wt[j + 2], w3 = g_wt[j + 3];
        a0 = fmaf(w0, g_g[s0 * FC + c], a0);
        a1 = fmaf(w1, g_g[s1 * FC + c], a1);
        a2 = fmaf(w2, g_g[s2 * FC + c], a2);
        a3 = fmaf(w3, g_g[s3 * FC + c], a3);
    }
    for (; j < end; j++)
        a0 = fmaf(g_wt[j], g_g[g_es[j] * FC + c], a0);

    float di = g_dinv[node];
    out[node * FC + c] = (a0 + a1) + (a2 + a3) + di * di * g_g[node * FC + c] + b2[c];
}

// ---------------- launch (kernel launches ONLY) ----------------
extern "C" void kernel_launch(void* const* d_in, const int* in_sizes, int n_in,
                              void* d_out, int out_size) {
    const float* x   = (const float*)d_in[0];
    const void*  ei  = d_in[1];              // [2, NE] int32 OR int64 — detected on device
    const float* W1  = (const float*)d_in[2];
    const float* b1  = (const float*)d_in[3];
    const float* W2  = (const float*)d_in[4];
    const float* b2  = (const float*)d_in[5];
    float*       out = (float*)d_out;

    // dtype detection + CSR build + norm
    k_detect  <<<1, 32>>>((const int*)ei);
    k_zero_deg<<<(NN + 255) / 256, 256>>>();
    k_hist    <<<(NE + 255) / 256, 256>>>(ei);
    k_scan    <<<1, 256>>>();
    k_dinv    <<<(NN + 255) / 256, 256>>>();
    k_scatter <<<(NE + 255) / 256, 256>>>(ei);

    // layer 1
    k_gemm1<<<(NN + 63) / 64, 256>>>(x, W1);
    k_agg1 <<<NN, 128>>>(b1);

    // layer 2
    k_gemm2<<<(NN + 127) / 128, 256>>>(W2);
    k_agg2 <<<NN, 64>>>(b2, out);
}

// round 16
// speedup vs baseline: 1.2292x; 1.2292x over previous
#include <cuda_runtime.h>

#define NN 100000
#define NE 3200000
#define FH  128
#define FC  40
#define NB  ((NN + 255) / 256)   // 391 blocks over nodes

typedef long long ll;

// ---------------- scratch (device globals, no allocation) ----------------
__device__ int   g_is64;             // 1 if edge_index is int64, 0 if int32
__device__ int   g_deg[NN];          // in-degree (real edges)
__device__ int   g_bsum[NB];         // per-block degree sums
__device__ int   g_bpre[NB];         // exclusive prefix of block sums
__device__ int   g_off[NN + 1];      // CSR row offsets
__device__ int   g_cur[NN];          // scatter cursors
__device__ int   g_es[NE];           // CSR: src node per slot
__device__ float g_wt[NE];           // CSR: edge weight per slot
__device__ float g_dinv[NN];         // rsqrt(deg+1)
__device__ float g_h [NN * FH];      // x @ W1
__device__ float g_h1[NN * FH];      // relu(agg1 + b1)
__device__ float g_g [NN * FC];      // h1 @ W2

// ---------------- dtype detection (odd words all zero => int64) ----------------
__global__ void k_detect(const int* ei32) {
    if (threadIdx.x == 0) {
        int all0 = 1;
        for (int i = 1; i < 129; i += 2) all0 &= (ei32[i] == 0);
        g_is64 = all0;
    }
}

__device__ __forceinline__ int edge_at(const void* ei, int idx) {
    if (g_is64) return (int)((const ll*)ei)[idx];
    return ((const int*)ei)[idx];
}

// ---------------- degree histogram ----------------
__global__ void k_zero_deg() {
    int i = blockIdx.x * 256 + threadIdx.x;
    if (i < NN) g_deg[i] = 0;
}

__global__ void k_hist(const void* ei) {
    int i = blockIdx.x * 256 + threadIdx.x;
    if (i < NE) atomicAdd(&g_deg[edge_at(ei, NE + i)], 1);
}

// ---------------- scan pass 1: per-block sums ----------------
__global__ void k_blocksum() {
    int i = blockIdx.x * 256 + threadIdx.x;
    int v = (i < NN) ? g_deg[i] : 0;
    __shared__ int ws[8];
#pragma unroll
    for (int o = 16; o > 0; o >>= 1) v += __shfl_down_sync(0xffffffffu, v, o);
    if ((threadIdx.x & 31) == 0) ws[threadIdx.x >> 5] = v;
    __syncthreads();
    if (threadIdx.x < 8) {
        int s = ws[threadIdx.x];
#pragma unroll
        for (int o = 4; o > 0; o >>= 1) s += __shfl_down_sync(0xffu, s, o);
        if (threadIdx.x == 0) g_bsum[blockIdx.x] = s;
    }
}

// ---------------- scan pass 2: scan 391 block sums in one block ----------------
__global__ void k_scanb() {
    __shared__ int sm[512];
    int t = threadIdx.x;
    sm[t] = (t < NB) ? g_bsum[t] : 0;
    __syncthreads();
    for (int d = 1; d < 512; d <<= 1) {
        int v = (t >= d) ? sm[t - d] : 0;
        __syncthreads();
        sm[t] += v;
        __syncthreads();
    }
    if (t < NB) g_bpre[t] = sm[t] - g_bsum[t];   // exclusive
}

// ---------------- scan pass 3: intra-block scan -> offsets, cursors, dinv ------
__global__ void k_offsets() {
    int i = blockIdx.x * 256 + threadIdx.x;
    int t = threadIdx.x;
    int lane = t & 31, warp = t >> 5;
    int d = (i < NN) ? g_deg[i] : 0;

    // warp inclusive scan
    int v = d;
#pragma unroll
    for (int o = 1; o < 32; o <<= 1) {
        int u = __shfl_up_sync(0xffffffffu, v, o);
        if (lane >= o) v += u;
    }
    __shared__ int wsum[8];
    if (lane == 31) wsum[warp] = v;
    __syncthreads();
    if (t < 8) {
        int s = wsum[t];
#pragma unroll
        for (int o = 1; o < 8; o <<= 1) {
            int u = __shfl_up_sync(0xffu, s, o);
            if (t >= o) s += u;
        }
        wsum[t] = s;
    }
    __syncthreads();
    int excl = v - d + (warp ? wsum[warp - 1] : 0) + g_bpre[blockIdx.x];

    if (i < NN) {
        g_off[i] = excl;
        g_cur[i] = excl;
        g_dinv[i] = rsqrtf((float)(d + 1));
        if (i == NN - 1) g_off[NN] = excl + d;
    }
}

// ---------------- scatter edges into CSR buckets ----------------
__global__ void k_scatter(const void* ei) {
    int e = blockIdx.x * 256 + threadIdx.x;
    if (e < NE) {
        int s = edge_at(ei, e);
        int d = edge_at(ei, NE + e);
        float w = g_dinv[s] * g_dinv[d];
        int pos = atomicAdd(&g_cur[d], 1);
        g_es[pos] = s;
        g_wt[pos] = w;
    }
}

// ---------------- GEMM1: g_h = x @ W1  (M=100000, K=128, N=128) ----------------
__global__ void k_gemm1(const float* __restrict__ x, const float* __restrict__ W) {
    __shared__ float xs[64][33];
    __shared__ float ws[32][132];

    int tid  = threadIdx.x;
    int row0 = blockIdx.x * 64;
    int ty = tid >> 4;
    int tx = tid & 15;

    float acc[4][8];
#pragma unroll
    for (int i = 0; i < 4; i++)
#pragma unroll
        for (int j = 0; j < 8; j++) acc[i][j] = 0.f;

    for (int kk = 0; kk < 128; kk += 32) {
        for (int i = tid; i < 64 * 32; i += 256) {
            int r = i >> 5, c = i & 31;
            int gr = row0 + r;
            xs[r][c] = (gr < NN) ? x[gr * 128 + kk + c] : 0.f;
        }
        for (int i = tid; i < 32 * 128; i += 256) {
            int r = i >> 7, c = i & 127;
            ws[r][c] = W[(kk + r) * 128 + c];
        }
        __syncthreads();

#pragma unroll
        for (int k = 0; k < 32; k++) {
            float a[4];
#pragma unroll
            for (int i = 0; i < 4; i++) a[i] = xs[ty * 4 + i][k];
            float b[8];
#pragma unroll
            for (int j = 0; j < 8; j++) b[j] = ws[k][tx + 16 * j];
#pragma unroll
            for (int i = 0; i < 4; i++)
#pragma unroll
                for (int j = 0; j < 8; j++) acc[i][j] = fmaf(a[i], b[j], acc[i][j]);
        }
        __syncthreads();
    }

#pragma unroll
    for (int i = 0; i < 4; i++) {
        int r = row0 + ty * 4 + i;
        if (r < NN) {
#pragma unroll
            for (int j = 0; j < 8; j++) g_h[r * 128 + tx + 16 * j] = acc[i][j];
        }
    }
}

// ---------------- agg layer 1: smem-staged edge tiles ----------------
__global__ void k_agg1(const float* __restrict__ b1) {
    int node = blockIdx.x;
    int c    = threadIdx.x;             // 0..127
    int beg  = g_off[node];
    int end  = g_off[node + 1];

    __shared__ int   ses[128];
    __shared__ float swt[128];

    float a0 = 0.f, a1 = 0.f, a2 = 0.f, a3 = 0.f;

    for (int base = beg; base < end; base += 128) {
        int n = min(128, end - base);
        __syncthreads();
        if (c < n) { ses[c] = g_es[base + c]; swt[c] = g_wt[base + c]; }
        __syncthreads();

        int j = 0;
        for (; j + 3 < n; j += 4) {
            a0 = fmaf(swt[j],     g_h[ses[j]     * FH + c], a0);
            a1 = fmaf(swt[j + 1], g_h[ses[j + 1] * FH + c], a1);
            a2 = fmaf(swt[j + 2], g_h[ses[j + 2] * FH + c], a2);
            a3 = fmaf(swt[j + 3], g_h[ses[j + 3] * FH + c], a3);
        }
        for (; j < n; j++)
            a0 = fmaf(swt[j], g_h[ses[j] * FH + c], a0);
    }

    float di = g_dinv[node];
    float acc = (a0 + a1) + (a2 + a3) + di * di * g_h[node * FH + c] + b1[c];
    g_h1[node * FH + c] = fmaxf(acc, 0.f);
}

// ---------------- GEMM2: g_g = h1 @ W2  (M=100000, K=128, N=40) ----------------
__global__ void k_gemm2(const float* __restrict__ W2) {
    __shared__ float hs[128][33];
    __shared__ float ws[32][40];

    int tid  = threadIdx.x;
    int row0 = blockIdx.x * 128;
    int ty = tid >> 3;
    int tx = tid & 7;

    float acc[4][5];
#pragma unroll
    for (int i = 0; i < 4; i++)
#pragma unroll
        for (int j = 0; j < 5; j++) acc[i][j] = 0.f;

    for (int kk = 0; kk < 128; kk += 32) {
        for (int i = tid; i < 128 * 32; i += 256) {
            int r = i >> 5, c = i & 31;
            int gr = row0 + r;
            hs[r][c] = (gr < NN) ? g_h1[gr * 128 + kk + c] : 0.f;
        }
        for (int i = tid; i < 32 * 40; i += 256) {
            int r = i / 40, c = i - r * 40;
            ws[r][c] = W2[(kk + r) * 40 + c];
        }
        __syncthreads();

#pragma unroll
        for (int k = 0; k < 32; k++) {
            float a[4];
#pragma unroll
            for (int i = 0; i < 4; i++) a[i] = hs[ty * 4 + i][k];
            float b[5];
#pragma unroll
            for (int j = 0; j < 5; j++) b[j] = ws[k][tx + 8 * j];
#pragma unroll
            for (int i = 0; i < 4; i++)
#pragma unroll
                for (int j = 0; j < 5; j++) acc[i][j] = fmaf(a[i], b[j], acc[i][j]);
        }
        __syncthreads();
    }

#pragma unroll
    for (int i = 0; i < 4; i++) {
        int r = row0 + ty * 4 + i;
        if (r < NN) {
#pragma unroll
            for (int j = 0; j < 5; j++) g_g[r * 40 + tx + 8 * j] = acc[i][j];
        }
    }
}

// ---------------- agg layer 2: 8 nodes per block, 40 lanes each ----------------
__global__ void k_agg2(const float* __restrict__ b2, float* __restrict__ out) {
    int t    = threadIdx.x;              // 0..319
    int node = blockIdx.x * 8 + t / FC;
    int c    = t % FC;
    if (node >= NN) return;

    int beg = g_off[node];
    int end = g_off[node + 1];

    float a0 = 0.f, a1 = 0.f, a2 = 0.f, a3 = 0.f;
    int j = beg;
    for (; j + 3 < end; j += 4) {
        int   s0 = g_es[j],     s1 = g_es[j + 1], s2 = g_es[j + 2], s3 = g_es[j + 3];
        float w0 = g_wt[j],     w1 = g_wt[j + 1], w2 = g_wt[j + 2], w3 = g_wt[j + 3];
        a0 = fmaf(w0, g_g[s0 * FC + c], a0);
        a1 = fmaf(w1, g_g[s1 * FC + c], a1);
        a2 = fmaf(w2, g_g[s2 * FC + c], a2);
        a3 = fmaf(w3, g_g[s3 * FC + c], a3);
    }
    for (; j < end; j++)
        a0 = fmaf(g_wt[j], g_g[g_es[j] * FC + c], a0);

    float di = g_dinv[node];
    out[node * FC + c] = (a0 + a1) + (a2 + a3) + di * di * g_g[node * FC + c] + b2[c];
}

// ---------------- launch (kernel launches ONLY) ----------------
extern "C" void kernel_launch(void* const* d_in, const int* in_sizes, int n_in,
                              void* d_out, int out_size) {
    const float* x   = (const float*)d_in[0];
    const void*  ei  = d_in[1];              // [2, NE] int32 or int64 (detected)
    const float* W1  = (const float*)d_in[2];
    const float* b1  = (const float*)d_in[3];
    const float* W2  = (const float*)d_in[4];
    const float* b2  = (const float*)d_in[5];
    float*       out = (float*)d_out;

    // CSR build + norm
    k_detect  <<<1, 32>>>((const int*)ei);
    k_zero_deg<<<NB, 256>>>();
    k_hist    <<<(NE + 255) / 256, 256>>>(ei);
    k_blocksum<<<NB, 256>>>();
    k_scanb   <<<1, 512>>>();
    k_offsets <<<NB, 256>>>();
    k_scatter <<<(NE + 255) / 256, 256>>>(ei);

    // layer 1
    k_gemm1<<<(NN + 63) / 64, 256>>>(x, W1);
    k_agg1 <<<NN, 128>>>(b1);

    // layer 2
    k_gemm2<<<(NN + 127) / 128, 256>>>(W2);
    k_agg2 <<<(NN + 7) / 8, 320>>>(b2, out);
}